// round 6
// baseline (speedup 1.0000x reference)
#include <cuda_runtime.h>
#include <cstdint>

// Problem constants
#define Bq  16
#define Cq  128
#define HWq 1024
#define Nq  16384   // B*H*W
#define Dq  64
#define Kq  8192

#define ZQ_ELEMS 1048576          // Nq*Dq  (z_q_st output, NCHW)
#define DIFF_OFF 1048576
#define IND_OFF  1048577

// ---- scratch (device globals; no allocation allowed) ----
__device__ float  g_ze[Nq * Dq];     // projected+BN z_e, row-major [N, D]
__device__ float4 g_et[16 * Kq];     // embed transposed: [seg=d/4][k] float4 (2 MB)
__device__ float  g_ce[Kq];          // ||e_k||^2
__device__ int    g_ind[Nq];         // argmin indices
__device__ float  g_part[256];       // per-block partial sums for diff

// Packed dual fp32 FMA (sm_10x): d.lo += a.lo*b.lo ; d.hi += a.hi*b.hi
// NOT volatile: let ptxas schedule + attach .reuse flags.
__device__ __forceinline__ void fma2(unsigned long long& d,
                                     unsigned long long a,
                                     unsigned long long b) {
    asm("fma.rn.f32x2 %0, %1, %2, %3;" : "=l"(d) : "l"(a), "l"(b), "l"(d));
}

__device__ __forceinline__ void cpa16(uint32_t s, const void* g) {
    asm volatile("cp.async.ca.shared.global [%0], [%1], 16;" :: "r"(s), "l"(g));
}
#define CPA_COMMIT() asm volatile("cp.async.commit_group;")
#define CPA_WAIT1()  asm volatile("cp.async.wait_group 1;")

// ============================================================
// Kernel A: z_e = BN(conv1x1(z))   [N, D] fp32
// ============================================================
__global__ __launch_bounds__(256) void k_proj(
    const float* __restrict__ z,   const float* __restrict__ w,
    const float* __restrict__ pb,  const float* __restrict__ gma,
    const float* __restrict__ bta, const float* __restrict__ rmn,
    const float* __restrict__ rvr)
{
    __shared__ float zsm[Cq * 32];   // [c][nn]
    __shared__ float wsm[Dq * Cq];   // [d][c]
    int tid = threadIdx.x;
    int n0  = blockIdx.x * 32;
    int b   = n0 >> 10, hw0 = n0 & 1023;

#pragma unroll
    for (int i = 0; i < 16; i++) {
        int idx = tid + i * 256;
        int c = idx >> 5, nn = idx & 31;
        zsm[idx] = z[(b * Cq + c) * HWq + hw0 + nn];
    }
#pragma unroll
    for (int i = 0; i < 32; i++) wsm[tid + i * 256] = w[tid + i * 256];
    __syncthreads();

    int lane = tid & 31, wd = tid >> 5;
    int d0 = wd * 8;
    float acc[8];
#pragma unroll
    for (int j = 0; j < 8; j++) acc[j] = 0.f;

#pragma unroll 4
    for (int c = 0; c < Cq; c++) {
        float a = zsm[c * 32 + lane];
#pragma unroll
        for (int j = 0; j < 8; j++)
            acc[j] = fmaf(a, wsm[(d0 + j) * Cq + c], acc[j]);
    }

    float o[8];
#pragma unroll
    for (int j = 0; j < 8; j++) {
        int d = d0 + j;
        float sc = gma[d] * (1.0f / sqrtf(rvr[d] + 1e-5f));
        float sh = bta[d] - rmn[d] * sc;
        o[j] = (acc[j] + pb[d]) * sc + sh;
    }
    float* dst = g_ze + (size_t)(n0 + lane) * Dq + d0;
    ((float4*)dst)[0] = make_float4(o[0], o[1], o[2], o[3]);
    ((float4*)dst)[1] = make_float4(o[4], o[5], o[6], o[7]);
}

// ============================================================
// Kernel P: transpose embed -> g_et [seg][k], and ce[k]=||e_k||^2
// ============================================================
__global__ __launch_bounds__(256) void k_prep(const float* __restrict__ embed)
{
    int id  = blockIdx.x * 256 + threadIdx.x;   // [0, Kq*16)
    int k   = id >> 4, seg = id & 15;
    float4 v = ((const float4*)embed)[id];
    g_et[seg * Kq + k] = v;
    float s = v.x * v.x + v.y * v.y + v.z * v.z + v.w * v.w;
    s += __shfl_xor_sync(0xffffffffu, s, 1);
    s += __shfl_xor_sync(0xffffffffu, s, 2);
    s += __shfl_xor_sync(0xffffffffu, s, 4);
    s += __shfl_xor_sync(0xffffffffu, s, 8);
    if (seg == 0) g_ce[k] = s;
}

// ============================================================
// Kernel C: argmin over K of (szz - 2*dot) + ce[k]
// 64 n-rows per CTA; 128-k chunks, cp.async double-buffered.
// Thread tile: 8n x 4k, f32x2 accumulators. Inner loop emits runs of
// 8 consecutive FFMA2 sharing the same b operand -> .reuse -> rt=2.
// ============================================================
__global__ __launch_bounds__(256, 2) void k_argmin(float* dummy)
{
    extern __shared__ float smem[];
    float*  zs  = smem;                       // 64*64 floats      (16384 B)
    float*  szz = smem + 4096;                // 64 floats (+pad to 16B)
    float4* es4 = (float4*)(smem + 4160);     // 2 bufs * 2048 f4  (65536 B)
    uint32_t es_u32 = (uint32_t)__cvta_generic_to_shared(es4);

    int tid = threadIdx.x;
    int tx  = tid & 31, ty = tid >> 5;
    int n0  = blockIdx.x * 64;

    // prologue: prefetch chunks 0 and 1
#pragma unroll
    for (int i = 0; i < 8; i++) {
        int id = tid + i * 256;
        int seg = id >> 7, kl = id & 127;
        cpa16(es_u32 + (uint32_t)id * 16u, &g_et[seg * Kq + kl]);
    }
    CPA_COMMIT();
#pragma unroll
    for (int i = 0; i < 8; i++) {
        int id = tid + i * 256;
        int seg = id >> 7, kl = id & 127;
        cpa16(es_u32 + (uint32_t)(2048 + id) * 16u, &g_et[seg * Kq + 128 + kl]);
    }
    CPA_COMMIT();

    {   // load z_e tile (4096 floats)
        const float4* src = (const float4*)(g_ze + (size_t)n0 * Dq);
        float4* dst4 = (float4*)zs;
#pragma unroll
        for (int i = 0; i < 4; i++) dst4[tid + i * 256] = src[tid + i * 256];
    }
    __syncthreads();
    if (tid < 64) {
        const float* r = zs + tid * Dq;
        float s = 0.f;
#pragma unroll
        for (int d = 0; d < Dq; d++) s = fmaf(r[d], r[d], s);
        szz[tid] = s;
    }

    float bestv[8]; int besti[8];
#pragma unroll
    for (int i = 0; i < 8; i++) { bestv[i] = 3.0e38f; besti[i] = 0; }

    const float* zrow = zs + ty * 8 * Dq;

    for (int c = 0; c < 64; c++) {
        CPA_WAIT1();
        __syncthreads();          // chunk c data + (c=0: szz) visible everywhere
        int buf = c & 1;
        const float4* eb = es4 + buf * 2048;

        float ce[4];
#pragma unroll
        for (int j = 0; j < 4; j++) ce[j] = __ldg(&g_ce[c * 128 + tx + 32 * j]);

        unsigned long long acc[8][4];
#pragma unroll
        for (int i = 0; i < 8; i++)
#pragma unroll
            for (int j = 0; j < 4; j++) acc[i][j] = 0ull;

#pragma unroll
        for (int dp2 = 0; dp2 < 16; dp2++) {
            unsigned long long b01[4], b23[4];
#pragma unroll
            for (int j = 0; j < 4; j++) {
                float4 b = eb[dp2 * 128 + tx + 32 * j];
                b01[j] = *(unsigned long long*)&b.x;
                b23[j] = *(unsigned long long*)&b.z;
            }
            // half 0: d-pair (2*dp2). 8 consecutive FFMA2 share b01[j] -> .reuse
            {
                unsigned long long a01[8];
#pragma unroll
                for (int i = 0; i < 8; i++)
                    a01[i] = *(const unsigned long long*)(zrow + i * Dq + dp2 * 4);
#pragma unroll
                for (int j = 0; j < 4; j++)
#pragma unroll
                    for (int i = 0; i < 8; i++) fma2(acc[i][j], a01[i], b01[j]);
            }
            // half 1: d-pair (2*dp2+1). Same per-accumulator order as before.
            {
                unsigned long long a23[8];
#pragma unroll
                for (int i = 0; i < 8; i++)
                    a23[i] = *(const unsigned long long*)(zrow + i * Dq + dp2 * 4 + 2);
#pragma unroll
                for (int j = 0; j < 4; j++)
#pragma unroll
                    for (int i = 0; i < 8; i++) fma2(acc[i][j], a23[i], b23[j]);
            }
        }

#pragma unroll
        for (int i = 0; i < 8; i++) {
            float s = szz[ty * 8 + i];
#pragma unroll
            for (int j = 0; j < 4; j++) {
                float2 p = *(float2*)&acc[i][j];
                // same rounding chain as reference: fl(szz - 2*dot) + ce
                float m = fmaf(-2.0f, p.x + p.y, s) + ce[j];
                if (m < bestv[i]) { bestv[i] = m; besti[i] = c * 128 + tx + 32 * j; }
            }
        }
        __syncthreads();          // everyone done reading buf before refill

        if (c + 2 < 64) {
#pragma unroll
            for (int i = 0; i < 8; i++) {
                int id = tid + i * 256;
                int seg = id >> 7, kl = id & 127;
                cpa16(es_u32 + (uint32_t)(buf * 2048 + id) * 16u,
                      &g_et[seg * Kq + (c + 2) * 128 + kl]);
            }
        }
        CPA_COMMIT();             // always commit (possibly empty) for wait accounting
    }

    // warp-reduce (tie-break: lowest index, matching jnp.argmax first-max)
#pragma unroll
    for (int i = 0; i < 8; i++) {
        float v = bestv[i]; int ix = besti[i];
#pragma unroll
        for (int o = 16; o; o >>= 1) {
            float ov = __shfl_xor_sync(0xffffffffu, v, o);
            int   oi = __shfl_xor_sync(0xffffffffu, ix, o);
            if (ov < v || (ov == v && oi < ix)) { v = ov; ix = oi; }
        }
        if (tx == 0) g_ind[n0 + ty * 8 + i] = ix;
    }
}

// ============================================================
// Kernel D: gather z_q, straight-through out (NCHW), ind, diff partials
// ============================================================
__global__ __launch_bounds__(64) void k_out(const float* __restrict__ embed,
                                            float* __restrict__ out, int out_size)
{
    __shared__ float red[64];
    int tid = threadIdx.x;
    int n   = blockIdx.x * 64 + tid;
    int b   = n >> 10, hw = n & 1023;
    int ind = g_ind[n];
    const float4* q4 = (const float4*)(embed + (size_t)ind * Dq);
    const float4* e4 = (const float4*)(g_ze + (size_t)n * Dq);
    float* ob = out + b * 65536 + hw;
    bool wrq = (out_size >= ZQ_ELEMS);
    float ss = 0.f;
#pragma unroll
    for (int i = 0; i < 16; i++) {
        float4 q = q4[i], e = e4[i];
        float dx = q.x - e.x, dy = q.y - e.y, dz = q.z - e.z, dw = q.w - e.w;
        ss += dx * dx + dy * dy + dz * dz + dw * dw;
        if (wrq) {
            ob[(4 * i + 0) * 1024] = e.x + dx;
            ob[(4 * i + 1) * 1024] = e.y + dy;
            ob[(4 * i + 2) * 1024] = e.z + dz;
            ob[(4 * i + 3) * 1024] = e.w + dw;
        }
    }
    if (out_size >= IND_OFF + Nq) out[IND_OFF + n] = (float)ind;

    red[tid] = ss;
    __syncthreads();
    for (int s = 32; s; s >>= 1) {
        if (tid < s) red[tid] += red[tid + s];
        __syncthreads();
    }
    if (tid == 0) g_part[blockIdx.x] = red[0];
}

// ============================================================
// Kernel E: deterministic final reduce -> diff scalar
// ============================================================
__global__ void k_diff(float* __restrict__ out, int out_size) {
    if (threadIdx.x == 0 && out_size >= DIFF_OFF + 1) {
        float s = 0.f;
        for (int i = 0; i < 256; i++) s += g_part[i];
        float m = s * (1.0f / 1048576.0f);           // mean over B*H*W*D
        out[DIFF_OFF] = 10.0f * (0.25f * m + m);     // KLD_SCALE*(COMMIT*m + m)
    }
}

extern "C" void kernel_launch(void* const* d_in, const int* in_sizes, int n_in,
                              void* d_out, int out_size)
{
    const float* z     = (const float*)d_in[0];   // [16,128,32,32]
    const float* pw    = (const float*)d_in[1];   // [64,128]
    const float* pb    = (const float*)d_in[2];   // [64]
    const float* gma   = (const float*)d_in[3];   // [64]
    const float* bta   = (const float*)d_in[4];   // [64]
    const float* rmn   = (const float*)d_in[5];   // [64]
    const float* rvr   = (const float*)d_in[6];   // [64]
    const float* embed = (const float*)d_in[7];   // [8192,64]
    float* out = (float*)d_out;

    static const int kArgSmem = 4160 * 4 + 2 * 2048 * 16;   // 82176 B
    cudaFuncSetAttribute(k_argmin, cudaFuncAttributeMaxDynamicSharedMemorySize,
                         kArgSmem);

    k_proj  <<<Nq / 32, 256>>>(z, pw, pb, gma, bta, rmn, rvr);
    k_prep  <<<Kq * 16 / 256, 256>>>(embed);
    k_argmin<<<Nq / 64, 256, kArgSmem>>>(out);
    k_out   <<<Nq / 64, 64>>>(embed, out, out_size);
    k_diff  <<<1, 32>>>(out, out_size);
}

// round 7
// speedup vs baseline: 1.4587x; 1.4587x over previous
#include <cuda_runtime.h>
#include <cuda_bf16.h>
#include <cstdint>

// Problem constants
#define Bq  16
#define Cq  128
#define HWq 1024
#define Nq  16384   // B*H*W
#define Dq  64
#define Kq  8192

#define ZQ_ELEMS 1048576          // Nq*Dq  (z_q_st output, NCHW)
#define DIFF_OFF 1048576
#define IND_OFF  1048577

#define EPSF 0.15f                // filter margin (~20 sigma of bf16 dot error)

// ---- scratch (device globals; no allocation allowed) ----
__device__ float          g_ze [Nq * Dq];   // projected+BN z_e fp32, [N][64]
__device__ __nv_bfloat16  g_zeb[Nq * Dq];   // z_e in bf16, [N][64]
__device__ __nv_bfloat16  g_eb [Kq * Dq];   // embed in bf16, [K][64]
__device__ float          g_ce [Kq];        // ||e_k||^2 (fp32, same chain as R3)
__device__ int            g_ind[Nq];        // argmin indices
__device__ float          g_part[256];      // per-block partials for diff

__device__ __forceinline__ void cpa16(uint32_t s, const void* g) {
    asm volatile("cp.async.ca.shared.global [%0], [%1], 16;" :: "r"(s), "l"(g));
}
#define CPA_COMMIT() asm volatile("cp.async.commit_group;")
#define CPA_WAIT1()  asm volatile("cp.async.wait_group 1;")
#define CPA_WAIT0()  asm volatile("cp.async.wait_group 0;")

__device__ __forceinline__ void mma16816(float& c0, float& c1, float& c2, float& c3,
                                         unsigned a0, unsigned a1, unsigned a2,
                                         unsigned a3, unsigned b0, unsigned b1) {
    asm("mma.sync.aligned.m16n8k16.row.col.f32.bf16.bf16.f32 "
        "{%0,%1,%2,%3}, {%4,%5,%6,%7}, {%8,%9}, {%0,%1,%2,%3};"
        : "+f"(c0), "+f"(c1), "+f"(c2), "+f"(c3)
        : "r"(a0), "r"(a1), "r"(a2), "r"(a3), "r"(b0), "r"(b1));
}

// order-preserving float<->uint for unsigned atomicMin
__device__ __forceinline__ unsigned ordf(float f) {
    unsigned u = __float_as_uint(f);
    return (u & 0x80000000u) ? ~u : (u | 0x80000000u);
}
__device__ __forceinline__ float deordf(unsigned u) {
    return (u & 0x80000000u) ? __uint_as_float(u & 0x7FFFFFFFu)
                             : __uint_as_float(~u);
}

// ============================================================
// Kernel A: z_e = BN(conv1x1(z))  -> g_ze (fp32) and g_zeb (bf16)
// ============================================================
__global__ __launch_bounds__(256) void k_proj(
    const float* __restrict__ z,   const float* __restrict__ w,
    const float* __restrict__ pb,  const float* __restrict__ gma,
    const float* __restrict__ bta, const float* __restrict__ rmn,
    const float* __restrict__ rvr)
{
    __shared__ float zsm[Cq * 32];   // [c][nn]
    __shared__ float wsm[Dq * Cq];   // [d][c]
    int tid = threadIdx.x;
    int n0  = blockIdx.x * 32;
    int b   = n0 >> 10, hw0 = n0 & 1023;

#pragma unroll
    for (int i = 0; i < 16; i++) {
        int idx = tid + i * 256;
        int c = idx >> 5, nn = idx & 31;
        zsm[idx] = z[(b * Cq + c) * HWq + hw0 + nn];
    }
#pragma unroll
    for (int i = 0; i < 32; i++) wsm[tid + i * 256] = w[tid + i * 256];
    __syncthreads();

    int lane = tid & 31, wd = tid >> 5;
    int d0 = wd * 8;
    float acc[8];
#pragma unroll
    for (int j = 0; j < 8; j++) acc[j] = 0.f;

#pragma unroll 4
    for (int c = 0; c < Cq; c++) {
        float a = zsm[c * 32 + lane];
#pragma unroll
        for (int j = 0; j < 8; j++)
            acc[j] = fmaf(a, wsm[(d0 + j) * Cq + c], acc[j]);
    }

    float o[8];
#pragma unroll
    for (int j = 0; j < 8; j++) {
        int d = d0 + j;
        float sc = gma[d] * (1.0f / sqrtf(rvr[d] + 1e-5f));
        float sh = bta[d] - rmn[d] * sc;
        o[j] = (acc[j] + pb[d]) * sc + sh;
    }
    float* dst = g_ze + (size_t)(n0 + lane) * Dq + d0;
    ((float4*)dst)[0] = make_float4(o[0], o[1], o[2], o[3]);
    ((float4*)dst)[1] = make_float4(o[4], o[5], o[6], o[7]);

    __nv_bfloat162 p[4];
#pragma unroll
    for (int j = 0; j < 4; j++)
        p[j] = __float22bfloat162_rn(make_float2(o[2 * j], o[2 * j + 1]));
    *(uint4*)(g_zeb + (size_t)(n0 + lane) * Dq + d0) = *(uint4*)p;
}

// ============================================================
// Kernel P: embed -> g_eb (bf16) and ce[k]=||e_k||^2 (fp32, R3 chain)
// ============================================================
__global__ __launch_bounds__(256) void k_prep(const float* __restrict__ embed)
{
    int id  = blockIdx.x * 256 + threadIdx.x;   // [0, Kq*16)
    int k   = id >> 4, seg = id & 15;
    float4 v = ((const float4*)embed)[id];
    __nv_bfloat162 b0 = __float22bfloat162_rn(make_float2(v.x, v.y));
    __nv_bfloat162 b1 = __float22bfloat162_rn(make_float2(v.z, v.w));
    uint2 pk; pk.x = *(unsigned*)&b0; pk.y = *(unsigned*)&b1;
    *(uint2*)(g_eb + (size_t)k * Dq + seg * 4) = pk;

    float s = v.x * v.x + v.y * v.y + v.z * v.z + v.w * v.w;
    s += __shfl_xor_sync(0xffffffffu, s, 1);
    s += __shfl_xor_sync(0xffffffffu, s, 2);
    s += __shfl_xor_sync(0xffffffffu, s, 4);
    s += __shfl_xor_sync(0xffffffffu, s, 8);
    if (seg == 0) g_ce[k] = s;
}

// ============================================================
// Kernel C: argmin via bf16 MMA filter + exact fp32 rescore
// CTA: 64 rows x all K. 8 warps: (w%4) -> m16 tile, (w/4) -> 32-code half.
// Chunk = 64 codes, cp.async double buffered; two sweeps.
// ============================================================

// smem byte offsets (all 16B aligned)
#define SM_ZS    0        // fp32 z tile   [64][68]f      -> 17408 B
#define SM_ZSB   17408    // bf16 z tile   [64][72]bf16   ->  9216 B
#define SM_EB    26624    // bf16 e chunk  2x[64][72]     -> 18432 B
#define SM_CE    45056    // ce chunk      2x64 f         ->   512 B
#define SM_MROW  45568    // unsigned[64]                 ->   256 B
#define SM_KEYS  45824    // ull[64]                      ->   512 B
#define SM_SZZ   46336    // float[64]                    ->   256 B
#define SM_TOTAL 46592
#define EBBUF    9216

__device__ __forceinline__ void rescore(const float* zr, float szzr,
                                        const float* __restrict__ embed,
                                        int kglob, unsigned long long* keyp)
{
    const float* er = embed + (size_t)kglob * Dq;
    float lo = 0.f, hi = 0.f;
#pragma unroll
    for (int d = 0; d < 32; d++) {          // even/odd split, same chain as R3
        lo = fmaf(zr[2 * d],     __ldg(er + 2 * d),     lo);
        hi = fmaf(zr[2 * d + 1], __ldg(er + 2 * d + 1), hi);
    }
    float m = fmaf(-2.0f, lo + hi, szzr) + __ldg(&g_ce[kglob]);
    unsigned long long key =
        ((unsigned long long)ordf(m) << 32) | (unsigned)kglob;
    atomicMin(keyp, key);
}

__global__ __launch_bounds__(256, 2) void k_argmin(const float* __restrict__ embed)
{
    extern __shared__ char sm[];
    float*              zs   = (float*)(sm + SM_ZS);
    char*               zsbB = sm + SM_ZSB;
    char*               ebB  = sm + SM_EB;
    float*              cesm = (float*)(sm + SM_CE);
    unsigned*           mrow = (unsigned*)(sm + SM_MROW);
    unsigned long long* keys = (unsigned long long*)(sm + SM_KEYS);
    float*              szz  = (float*)(sm + SM_SZZ);
    uint32_t smemu = (uint32_t)__cvta_generic_to_shared(sm);

    int tid = threadIdx.x;
    int l   = tid & 31, w = tid >> 5;
    int n0  = blockIdx.x * 64;
    int mbase = (w & 3) * 16;           // m16 tile
    int nhalf = (w >> 2) * 32;          // 32-code half of chunk
    int lg = l >> 2, lq = l & 3;        // fragment coords

    // ---- load z tiles ----
#pragma unroll
    for (int i = 0; i < 4; i++) {       // fp32 [64][68]
        int id = tid + i * 256;
        int r = id >> 4, s = id & 15;
        *(float4*)(zs + r * 68 + s * 4) =
            *(const float4*)(g_ze + (size_t)(n0 + r) * Dq + s * 4);
    }
#pragma unroll
    for (int i = 0; i < 2; i++) {       // bf16 [64][72]
        int g = tid + i * 256;
        int r = g >> 3, s = g & 7;
        *(uint4*)(zsbB + r * 144 + s * 16) =
            *(const uint4*)(g_zeb + (size_t)(n0 + r) * Dq + s * 8);
    }
    if (tid < 64) { mrow[tid] = 0xFFFFFFFFu; keys[tid] = ~0ull; }
    __syncthreads();
    if (tid < 64) {
        const float* r = zs + tid * 68;
        float s = 0.f;
#pragma unroll
        for (int d = 0; d < Dq; d++) s = fmaf(r[d], r[d], s);
        szz[tid] = s;
    }

    // prefetch helper (chunk c -> buffer buf)
    auto prefetch = [&](int c, int buf) {
#pragma unroll
        for (int i = 0; i < 2; i++) {
            int g = tid + i * 256;          // 0..511
            int code = g >> 3, seg = g & 7;
            cpa16(smemu + SM_EB + buf * EBBUF + code * 144 + seg * 16,
                  g_eb + (size_t)(c * 64 + code) * Dq + seg * 8);
        }
        if (tid < 16)
            cpa16(smemu + SM_CE + buf * 256 + tid * 16, g_ce + c * 64 + tid * 4);
    };

    float best0 = 3.0e38f, best1 = 3.0e38f;
    float thr0 = 0.f, thr1 = 0.f;

    for (int sweep = 0; sweep < 2; sweep++) {
        prefetch(0, 0); CPA_COMMIT();
        prefetch(1, 1); CPA_COMMIT();

        for (int c = 0; c < 128; c++) {
            CPA_WAIT1();
            __syncthreads();
            int buf = c & 1;
            const char*  eb = ebB + buf * EBBUF;
            const float* ce = cesm + buf * 64;

            // A fragments (shared across n-tiles)
            unsigned af[4][4];
#pragma unroll
            for (int ks = 0; ks < 4; ks++) {
                int cb = (ks * 16 + lq * 2) * 2;       // byte col
                int r0 = mbase + lg;
                af[ks][0] = *(const unsigned*)(zsbB + r0 * 144 + cb);
                af[ks][1] = *(const unsigned*)(zsbB + (r0 + 8) * 144 + cb);
                af[ks][2] = *(const unsigned*)(zsbB + r0 * 144 + cb + 16);
                af[ks][3] = *(const unsigned*)(zsbB + (r0 + 8) * 144 + cb + 16);
            }

#pragma unroll
            for (int nt = 0; nt < 4; nt++) {
                float c0 = 0.f, c1 = 0.f, c2 = 0.f, c3 = 0.f;
                int crow = nhalf + nt * 8 + lg;
#pragma unroll
                for (int ks = 0; ks < 4; ks++) {
                    int cb = (ks * 16 + lq * 2) * 2;
                    unsigned b0 = *(const unsigned*)(eb + crow * 144 + cb);
                    unsigned b1 = *(const unsigned*)(eb + crow * 144 + cb + 16);
                    mma16816(c0, c1, c2, c3,
                             af[ks][0], af[ks][1], af[ks][2], af[ks][3], b0, b1);
                }
                int cloc = nhalf + nt * 8 + 2 * lq;    // this thread's code pair
                float2 cp = *(const float2*)(ce + cloc);
                float s0 = fmaf(-2.f, c0, cp.x);
                float s1 = fmaf(-2.f, c1, cp.y);
                float s2 = fmaf(-2.f, c2, cp.x);
                float s3 = fmaf(-2.f, c3, cp.y);
                if (sweep == 0) {
                    best0 = fminf(best0, fminf(s0, s1));
                    best1 = fminf(best1, fminf(s2, s3));
                } else {
                    int kb = c * 64 + cloc;
                    int r0 = mbase + lg;
                    if (s0 <= thr0) rescore(zs + r0 * 68, szz[r0], embed, kb, &keys[r0]);
                    if (s1 <= thr0) rescore(zs + r0 * 68, szz[r0], embed, kb + 1, &keys[r0]);
                    if (s2 <= thr1) rescore(zs + (r0 + 8) * 68, szz[r0 + 8], embed, kb, &keys[r0 + 8]);
                    if (s3 <= thr1) rescore(zs + (r0 + 8) * 68, szz[r0 + 8], embed, kb + 1, &keys[r0 + 8]);
                }
            }
            __syncthreads();
            if (c + 2 < 128) prefetch(c + 2, buf);
            CPA_COMMIT();
        }

        if (sweep == 0) {
            // reduce per-row approx min -> mrow
            best0 = fminf(best0, __shfl_xor_sync(0xffffffffu, best0, 1));
            best0 = fminf(best0, __shfl_xor_sync(0xffffffffu, best0, 2));
            best1 = fminf(best1, __shfl_xor_sync(0xffffffffu, best1, 1));
            best1 = fminf(best1, __shfl_xor_sync(0xffffffffu, best1, 2));
            if (lq == 0) {
                atomicMin(&mrow[mbase + lg], ordf(best0));
                atomicMin(&mrow[mbase + lg + 8], ordf(best1));
            }
            CPA_WAIT0();
            __syncthreads();
            thr0 = deordf(mrow[mbase + lg]) + EPSF;
            thr1 = deordf(mrow[mbase + lg + 8]) + EPSF;
        }
    }

    CPA_WAIT0();
    __syncthreads();
    if (tid < 64) g_ind[n0 + tid] = (int)(keys[tid] & 0xFFFFFFFFu);
}

// ============================================================
// Kernel D: gather z_q, straight-through out (NCHW), ind, diff partials
// ============================================================
__global__ __launch_bounds__(64) void k_out(const float* __restrict__ embed,
                                            float* __restrict__ out, int out_size)
{
    __shared__ float red[64];
    int tid = threadIdx.x;
    int n   = blockIdx.x * 64 + tid;
    int b   = n >> 10, hw = n & 1023;
    int ind = g_ind[n];
    const float4* q4 = (const float4*)(embed + (size_t)ind * Dq);
    const float4* e4 = (const float4*)(g_ze + (size_t)n * Dq);
    float* ob = out + b * 65536 + hw;
    bool wrq = (out_size >= ZQ_ELEMS);
    float ss = 0.f;
#pragma unroll
    for (int i = 0; i < 16; i++) {
        float4 q = q4[i], e = e4[i];
        float dx = q.x - e.x, dy = q.y - e.y, dz = q.z - e.z, dw = q.w - e.w;
        ss += dx * dx + dy * dy + dz * dz + dw * dw;
        if (wrq) {
            ob[(4 * i + 0) * 1024] = e.x + dx;
            ob[(4 * i + 1) * 1024] = e.y + dy;
            ob[(4 * i + 2) * 1024] = e.z + dz;
            ob[(4 * i + 3) * 1024] = e.w + dw;
        }
    }
    if (out_size >= IND_OFF + Nq) out[IND_OFF + n] = (float)ind;

    red[tid] = ss;
    __syncthreads();
    for (int s = 32; s; s >>= 1) {
        if (tid < s) red[tid] += red[tid + s];
        __syncthreads();
    }
    if (tid == 0) g_part[blockIdx.x] = red[0];
}

// ============================================================
// Kernel E: deterministic final reduce -> diff scalar
// ============================================================
__global__ void k_diff(float* __restrict__ out, int out_size) {
    if (threadIdx.x == 0 && out_size >= DIFF_OFF + 1) {
        float s = 0.f;
        for (int i = 0; i < 256; i++) s += g_part[i];
        float m = s * (1.0f / 1048576.0f);           // mean over B*H*W*D
        out[DIFF_OFF] = 10.0f * (0.25f * m + m);     // KLD_SCALE*(COMMIT*m + m)
    }
}

extern "C" void kernel_launch(void* const* d_in, const int* in_sizes, int n_in,
                              void* d_out, int out_size)
{
    const float* z     = (const float*)d_in[0];   // [16,128,32,32]
    const float* pw    = (const float*)d_in[1];   // [64,128]
    const float* pb    = (const float*)d_in[2];   // [64]
    const float* gma   = (const float*)d_in[3];   // [64]
    const float* bta   = (const float*)d_in[4];   // [64]
    const float* rmn   = (const float*)d_in[5];   // [64]
    const float* rvr   = (const float*)d_in[6];   // [64]
    const float* embed = (const float*)d_in[7];   // [8192,64]
    float* out = (float*)d_out;

    cudaFuncSetAttribute(k_argmin, cudaFuncAttributeMaxDynamicSharedMemorySize,
                         SM_TOTAL);

    k_proj  <<<Nq / 32, 256>>>(z, pw, pb, gma, bta, rmn, rvr);
    k_prep  <<<Kq * 16 / 256, 256>>>(embed);
    k_argmin<<<Nq / 64, 256, SM_TOTAL>>>(embed);
    k_out   <<<Nq / 64, 64>>>(embed, out, out_size);
    k_diff  <<<1, 32>>>(out, out_size);
}